// round 1
// baseline (speedup 1.0000x reference)
#include <cuda_runtime.h>

#define D1 784
#define G1 196   // D1/4
#define N1 128
#define D2 128
#define G2 32
#define N2 64
#define D3 64
#define G3 16
#define N3 10
#define MT 32    // tokens per block
#define NT 256
#define NPART 256
#define WCHUNK 16  // k-groups of weights staged in smem at a time

// Packed ternary weights (s8x4 per int), transposed layouts for vector loads.
__device__ __align__(16) int g_wq1[G1 * N1];   // [kgroup][j]
__device__ __align__(16) int g_wq2[G2 * N2];   // [kgroup][j]
__device__ __align__(16) int g_wq3[N3 * G3];   // [j][kgroup]
__device__ float g_part1[NPART], g_part2[NPART], g_part3[NPART];
__device__ float g_cw[3];   // clip(mean|w|, 1e-5) per layer (dequant factor)

__device__ __forceinline__ int qact(float v) {
    int q = __float2int_rn(v);
    return max(-128, min(127, q));
}
__device__ __forceinline__ int qw(float w, float s) {
    int q = __float2int_rn(w * s);
    return max(-1, min(1, q));
}

// ---------------- prep: deterministic mean(|w|) partials ----------------
__global__ void prep_partial(const float* __restrict__ w1,
                             const float* __restrict__ w2,
                             const float* __restrict__ w3) {
    __shared__ float red[NT];
    int t = threadIdx.x;
    int gid = blockIdx.x * NT + t;
    int stride = NPART * NT;
    float s1 = 0.f, s2 = 0.f, s3 = 0.f;
    for (int i = gid; i < N1 * D1; i += stride) s1 += fabsf(w1[i]);
    for (int i = gid; i < N2 * D2; i += stride) s2 += fabsf(w2[i]);
    for (int i = gid; i < N3 * D3; i += stride) s3 += fabsf(w3[i]);

    red[t] = s1; __syncthreads();
    for (int s = NT / 2; s > 0; s >>= 1) { if (t < s) red[t] += red[t + s]; __syncthreads(); }
    if (t == 0) g_part1[blockIdx.x] = red[0];
    __syncthreads();
    red[t] = s2; __syncthreads();
    for (int s = NT / 2; s > 0; s >>= 1) { if (t < s) red[t] += red[t + s]; __syncthreads(); }
    if (t == 0) g_part2[blockIdx.x] = red[0];
    __syncthreads();
    red[t] = s3; __syncthreads();
    for (int s = NT / 2; s > 0; s >>= 1) { if (t < s) red[t] += red[t + s]; __syncthreads(); }
    if (t == 0) g_part3[blockIdx.x] = red[0];
}

// ---------------- prep: finalize means, quantize w2/w3 ----------------
__global__ void prep_finalize(const float* __restrict__ w2,
                              const float* __restrict__ w3) {
    __shared__ float red[NT];
    __shared__ float s_sw2, s_sw3;
    int t = threadIdx.x;

    red[t] = g_part1[t]; __syncthreads();
    for (int s = NT / 2; s > 0; s >>= 1) { if (t < s) red[t] += red[t + s]; __syncthreads(); }
    if (t == 0) { float c = fmaxf(red[0] / (float)(N1 * D1), 1e-5f); g_cw[0] = c; }
    __syncthreads();
    red[t] = g_part2[t]; __syncthreads();
    for (int s = NT / 2; s > 0; s >>= 1) { if (t < s) red[t] += red[t + s]; __syncthreads(); }
    if (t == 0) { float c = fmaxf(red[0] / (float)(N2 * D2), 1e-5f); g_cw[1] = c; s_sw2 = 1.f / c; }
    __syncthreads();
    red[t] = g_part3[t]; __syncthreads();
    for (int s = NT / 2; s > 0; s >>= 1) { if (t < s) red[t] += red[t + s]; __syncthreads(); }
    if (t == 0) { float c = fmaxf(red[0] / (float)(N3 * D3), 1e-5f); g_cw[2] = c; s_sw3 = 1.f / c; }
    __syncthreads();

    float sw2 = s_sw2, sw3 = s_sw3;
    for (int idx = t; idx < G2 * N2; idx += NT) {
        int g = idx / N2, j = idx % N2;
        const float* wp = w2 + j * D2 + 4 * g;
        int p = (qw(wp[0], sw2) & 0xff)
              | ((qw(wp[1], sw2) & 0xff) << 8)
              | ((qw(wp[2], sw2) & 0xff) << 16)
              | ((qw(wp[3], sw2) & 0xff) << 24);
        g_wq2[idx] = p;
    }
    for (int idx = t; idx < N3 * G3; idx += NT) {
        int j = idx / G3, g = idx % G3;
        const float* wp = w3 + j * D3 + 4 * g;
        int p = (qw(wp[0], sw3) & 0xff)
              | ((qw(wp[1], sw3) & 0xff) << 8)
              | ((qw(wp[2], sw3) & 0xff) << 16)
              | ((qw(wp[3], sw3) & 0xff) << 24);
        g_wq3[idx] = p;
    }
}

// ---------------- prep: quantize w1 (parallel) ----------------
__global__ void prep_quant_w1(const float* __restrict__ w1) {
    int idx = blockIdx.x * NT + threadIdx.x;
    if (idx >= G1 * N1) return;
    float sw = 1.f / g_cw[0];
    int g = idx / N1, j = idx % N1;
    const float* wp = w1 + j * D1 + 4 * g;
    int p = (qw(wp[0], sw) & 0xff)
          | ((qw(wp[1], sw) & 0xff) << 8)
          | ((qw(wp[2], sw) & 0xff) << 16)
          | ((qw(wp[3], sw) & 0xff) << 24);
    g_wq1[idx] = p;
}

// ---------------- fused main kernel ----------------
__global__ __launch_bounds__(NT) void ffn_main(
    const float* __restrict__ x,
    const float* __restrict__ sc1,
    const float* __restrict__ sc2,
    const float* __restrict__ sc3,
    float* __restrict__ out)
{
    __shared__ int   s_xq[MT][G1];        // 25088 B
    __shared__ int   s_w[WCHUNK * N1];    //  8192 B
    __shared__ float s_scale1[D1];        //  3136 B
    __shared__ float s_scale2[D2];
    __shared__ float s_scale3[D3];
    __shared__ int   s_h1q[MT][G2];       //  4096 B
    __shared__ int   s_h2q[MT][G3];       //  2048 B
    __shared__ float s_c1[MT], s_c2[MT], s_c3[MT];

    const int t = threadIdx.x;
    const int warp = t >> 5, lane = t & 31;
    const float cw1 = g_cw[0], cw2 = g_cw[1], cw3 = g_cw[2];

    for (int i = t; i < D1; i += NT) s_scale1[i] = sc1[i];
    if (t < D2) s_scale2[t] = sc2[t];
    if (t < D3) s_scale3[t] = sc3[t];
    __syncthreads();

    // ---- phase 1: per-token RMSNorm + int8 absmax quant of x ----
    #pragma unroll 1
    for (int c = 0; c < 4; c++) {
        int ltok = warp * 4 + c;
        const float4* xr = (const float4*)(x + (size_t)(blockIdx.x * MT + ltok) * D1);
        float4 xv[7];
        float ssq = 0.f, amx = 0.f;
        #pragma unroll
        for (int i = 0; i < 7; i++) {
            int f = lane + 32 * i;
            xv[i] = make_float4(0.f, 0.f, 0.f, 0.f);
            if (f < G1) {
                float4 v = xr[f];
                float4 sv = *(const float4*)(&s_scale1[4 * f]);
                xv[i] = v;
                ssq += v.x * v.x + v.y * v.y + v.z * v.z + v.w * v.w;
                amx = fmaxf(amx, fmaxf(fmaxf(fabsf(sv.x * v.x), fabsf(sv.y * v.y)),
                                       fmaxf(fabsf(sv.z * v.z), fabsf(sv.w * v.w))));
            }
        }
        #pragma unroll
        for (int m = 16; m > 0; m >>= 1) {
            ssq += __shfl_xor_sync(0xffffffffu, ssq, m);
            amx = fmaxf(amx, __shfl_xor_sync(0xffffffffu, amx, m));
        }
        float rms = sqrtf(ssq) * (1.0f / 28.0f);     // sqrt(784)=28
        float inv = 1.0f / (rms + 1e-8f);
        float amc = fmaxf(amx * inv, 1e-5f);
        float sq = 127.0f / amc;
        if (lane == 0) s_c1[ltok] = amc * (1.0f / 127.0f) * cw1;
        float fq = inv * sq;
        #pragma unroll
        for (int i = 0; i < 7; i++) {
            int f = lane + 32 * i;
            if (f < G1) {
                float4 sv = *(const float4*)(&s_scale1[4 * f]);
                float4 v = xv[i];
                int p = (qact(sv.x * v.x * fq) & 0xff)
                      | ((qact(sv.y * v.y * fq) & 0xff) << 8)
                      | ((qact(sv.z * v.z * fq) & 0xff) << 16)
                      | ((qact(sv.w * v.w * fq) & 0xff) << 24);
                s_xq[ltok][f] = p;
            }
        }
    }
    __syncthreads();

    // ---- GEMM1: [MT x 128] = xq @ wq1^T, dp4a, smem-staged weights ----
    const int tj = t & 15;          // j-group: j = tj*8 .. tj*8+7
    const int tm = t >> 4;          // token pair: tokens tm*2, tm*2+1
    const int tok0 = tm * 2, tok1 = tok0 + 1;

    int acc[2][8];
    #pragma unroll
    for (int c = 0; c < 2; c++)
        #pragma unroll
        for (int j = 0; j < 8; j++) acc[c][j] = 0;

    for (int f0 = 0; f0 < G1; f0 += WCHUNK) {
        int cnt = min(WCHUNK, G1 - f0);
        for (int idx = t; idx < cnt * N1 / 4; idx += NT)
            ((int4*)s_w)[idx] = ((const int4*)(g_wq1 + f0 * N1))[idx];
        __syncthreads();
        #pragma unroll 4
        for (int ff = 0; ff < cnt; ff++) {
            int a0 = s_xq[tok0][f0 + ff];
            int a1 = s_xq[tok1][f0 + ff];
            const int* wp = s_w + ff * N1 + tj * 8;
            int4 wA = *(const int4*)wp;
            int4 wB = *(const int4*)(wp + 4);
            acc[0][0] = __dp4a(a0, wA.x, acc[0][0]); acc[0][1] = __dp4a(a0, wA.y, acc[0][1]);
            acc[0][2] = __dp4a(a0, wA.z, acc[0][2]); acc[0][3] = __dp4a(a0, wA.w, acc[0][3]);
            acc[0][4] = __dp4a(a0, wB.x, acc[0][4]); acc[0][5] = __dp4a(a0, wB.y, acc[0][5]);
            acc[0][6] = __dp4a(a0, wB.z, acc[0][6]); acc[0][7] = __dp4a(a0, wB.w, acc[0][7]);
            acc[1][0] = __dp4a(a1, wA.x, acc[1][0]); acc[1][1] = __dp4a(a1, wA.y, acc[1][1]);
            acc[1][2] = __dp4a(a1, wA.z, acc[1][2]); acc[1][3] = __dp4a(a1, wA.w, acc[1][3]);
            acc[1][4] = __dp4a(a1, wB.x, acc[1][4]); acc[1][5] = __dp4a(a1, wB.y, acc[1][5]);
            acc[1][6] = __dp4a(a1, wB.z, acc[1][6]); acc[1][7] = __dp4a(a1, wB.w, acc[1][7]);
        }
        __syncthreads();
    }

    // ---- epilogue 1: dequant, relu, RMSNorm(128) + quant for layer 2 ----
    {
        float rr[2][8];
        #pragma unroll
        for (int c = 0; c < 2; c++) {
            float cf = s_c1[tm * 2 + c];
            float ssq = 0.f, amx = 0.f;
            #pragma unroll
            for (int j = 0; j < 8; j++) {
                float h = fmaxf((float)acc[c][j] * cf, 0.f);
                rr[c][j] = h;
                ssq += h * h;
                amx = fmaxf(amx, fabsf(s_scale2[tj * 8 + j] * h));
            }
            #pragma unroll
            for (int m = 1; m < 16; m <<= 1) {
                ssq += __shfl_xor_sync(0xffffffffu, ssq, m);
                amx = fmaxf(amx, __shfl_xor_sync(0xffffffffu, amx, m));
            }
            float rms = sqrtf(ssq) * 0.08838834764831845f;  // 1/sqrt(128)
            float inv = 1.0f / (rms + 1e-8f);
            float amc = fmaxf(amx * inv, 1e-5f);
            float sq = 127.0f / amc;
            if (tj == 0) s_c2[tm * 2 + c] = amc * (1.0f / 127.0f) * cw2;
            float fq = inv * sq;
            #pragma unroll
            for (int g = 0; g < 2; g++) {
                int p = 0;
                #pragma unroll
                for (int b = 0; b < 4; b++) {
                    int jj = g * 4 + b;
                    p |= (qact(s_scale2[tj * 8 + jj] * rr[c][jj] * fq) & 0xff) << (8 * b);
                }
                s_h1q[tm * 2 + c][tj * 2 + g] = p;
            }
        }
    }
    __syncthreads();

    // ---- GEMM2: [MT x 64] = h1q @ wq2^T ----
    int acc2[2][4];
    #pragma unroll
    for (int c = 0; c < 2; c++)
        #pragma unroll
        for (int j = 0; j < 4; j++) acc2[c][j] = 0;

    #pragma unroll 4
    for (int g = 0; g < G2; g++) {
        int a0 = s_h1q[tok0][g];
        int a1 = s_h1q[tok1][g];
        int4 w = *(const int4*)(g_wq2 + g * N2 + tj * 4);
        acc2[0][0] = __dp4a(a0, w.x, acc2[0][0]); acc2[0][1] = __dp4a(a0, w.y, acc2[0][1]);
        acc2[0][2] = __dp4a(a0, w.z, acc2[0][2]); acc2[0][3] = __dp4a(a0, w.w, acc2[0][3]);
        acc2[1][0] = __dp4a(a1, w.x, acc2[1][0]); acc2[1][1] = __dp4a(a1, w.y, acc2[1][1]);
        acc2[1][2] = __dp4a(a1, w.z, acc2[1][2]); acc2[1][3] = __dp4a(a1, w.w, acc2[1][3]);
    }

    // ---- epilogue 2: dequant, relu, RMSNorm(64) + quant for layer 3 ----
    {
        float r2[2][4];
        #pragma unroll
        for (int c = 0; c < 2; c++) {
            float cf = s_c2[tm * 2 + c];
            float ssq = 0.f, amx = 0.f;
            #pragma unroll
            for (int j = 0; j < 4; j++) {
                float h = fmaxf((float)acc2[c][j] * cf, 0.f);
                r2[c][j] = h;
                ssq += h * h;
                amx = fmaxf(amx, fabsf(s_scale3[tj * 4 + j] * h));
            }
            #pragma unroll
            for (int m = 1; m < 16; m <<= 1) {
                ssq += __shfl_xor_sync(0xffffffffu, ssq, m);
                amx = fmaxf(amx, __shfl_xor_sync(0xffffffffu, amx, m));
            }
            float rms = sqrtf(ssq) * 0.125f;  // 1/sqrt(64)
            float inv = 1.0f / (rms + 1e-8f);
            float amc = fmaxf(amx * inv, 1e-5f);
            float sq = 127.0f / amc;
            if (tj == 0) s_c3[tm * 2 + c] = amc * (1.0f / 127.0f) * cw3;
            float fq = inv * sq;
            int p = 0;
            #pragma unroll
            for (int b = 0; b < 4; b++)
                p |= (qact(s_scale3[tj * 4 + b] * r2[c][b] * fq) & 0xff) << (8 * b);
            s_h2q[tm * 2 + c][tj] = p;
        }
    }
    __syncthreads();

    // ---- GEMM3: [MT x 10] = h2q @ wq3^T, write output ----
    for (int p = t; p < MT * N3; p += NT) {
        int ltok = p / N3, j = p % N3;
        int a3 = 0;
        #pragma unroll
        for (int g = 0; g < G3; g++)
            a3 = __dp4a(s_h2q[ltok][g], g_wq3[j * G3 + g], a3);
        out[(blockIdx.x * MT + ltok) * N3 + j] = (float)a3 * s_c3[ltok];
    }
}

extern "C" void kernel_launch(void* const* d_in, const int* in_sizes, int n_in,
                              void* d_out, int out_size) {
    const float* x   = (const float*)d_in[0];
    const float* w1  = (const float*)d_in[1];
    const float* sc1 = (const float*)d_in[2];
    const float* w2  = (const float*)d_in[3];
    const float* sc2 = (const float*)d_in[4];
    const float* w3  = (const float*)d_in[5];
    const float* sc3 = (const float*)d_in[6];
    float* out = (float*)d_out;

    int ntok = in_sizes[0] / D1;   // 65536

    prep_partial<<<NPART, NT>>>(w1, w2, w3);
    prep_finalize<<<1, NT>>>(w2, w3);
    prep_quant_w1<<<(G1 * N1 + NT - 1) / NT, NT>>>(w1);
    ffn_main<<<ntok / MT, NT>>>(x, sc1, sc2, sc3, out);
}

// round 2
// speedup vs baseline: 1.4201x; 1.4201x over previous
#include <cuda_runtime.h>

#define D1 784
#define G1 196   // D1/4
#define N1 128
#define D2 128
#define G2 32
#define N2 64
#define D3 64
#define G3 16
#define N3 10
#define MT 32    // tokens per block
#define MTP 36   // padded token stride for s_xqT (16B-aligned rows of 4 tokens)
#define NT 256
#define NPART 256
#define WCHUNK 16  // k-groups of weights staged in smem at a time

// Packed ternary weights (s8x4 per int), transposed layouts for vector loads.
__device__ __align__(16) int g_wq1[G1 * N1];   // [kgroup][j]
__device__ __align__(16) int g_wq2[G2 * N2];   // [kgroup][j]
__device__ __align__(16) int g_wq3[N3 * G3];   // [j][kgroup]
__device__ float g_part1[NPART], g_part2[NPART], g_part3[NPART];
__device__ float g_sw[3];   // s_w = 1/clip(mean|w|,1e-5)  (quant scale)
__device__ float g_dq[3];   // 1/s_w                        (dequant factor, ref order)

__device__ __forceinline__ int qact(float v) {
    int q = __float2int_rn(v);
    return max(-128, min(127, q));
}
__device__ __forceinline__ int qw(float w, float s) {
    int q = __float2int_rn(w * s);
    return max(-1, min(1, q));
}

// ---------------- prep: deterministic mean(|w|) partials ----------------
__global__ void prep_partial(const float* __restrict__ w1,
                             const float* __restrict__ w2,
                             const float* __restrict__ w3) {
    __shared__ float red[NT];
    int t = threadIdx.x;
    int gid = blockIdx.x * NT + t;
    int stride = NPART * NT;
    float s1 = 0.f, s2 = 0.f, s3 = 0.f;
    for (int i = gid; i < N1 * D1; i += stride) s1 += fabsf(w1[i]);
    for (int i = gid; i < N2 * D2; i += stride) s2 += fabsf(w2[i]);
    for (int i = gid; i < N3 * D3; i += stride) s3 += fabsf(w3[i]);

    red[t] = s1; __syncthreads();
    for (int s = NT / 2; s > 0; s >>= 1) { if (t < s) red[t] += red[t + s]; __syncthreads(); }
    if (t == 0) g_part1[blockIdx.x] = red[0];
    __syncthreads();
    red[t] = s2; __syncthreads();
    for (int s = NT / 2; s > 0; s >>= 1) { if (t < s) red[t] += red[t + s]; __syncthreads(); }
    if (t == 0) g_part2[blockIdx.x] = red[0];
    __syncthreads();
    red[t] = s3; __syncthreads();
    for (int s = NT / 2; s > 0; s >>= 1) { if (t < s) red[t] += red[t + s]; __syncthreads(); }
    if (t == 0) g_part3[blockIdx.x] = red[0];
}

// ---------------- prep: finalize means, quantize w2/w3 ----------------
__global__ void prep_finalize(const float* __restrict__ w2,
                              const float* __restrict__ w3) {
    __shared__ float red[NT];
    __shared__ float s_sw2, s_sw3;
    int t = threadIdx.x;

    red[t] = g_part1[t]; __syncthreads();
    for (int s = NT / 2; s > 0; s >>= 1) { if (t < s) red[t] += red[t + s]; __syncthreads(); }
    if (t == 0) {
        float c = fmaxf(red[0] / (float)(N1 * D1), 1e-5f);
        float sw = 1.0f / c; g_sw[0] = sw; g_dq[0] = 1.0f / sw;
    }
    __syncthreads();
    red[t] = g_part2[t]; __syncthreads();
    for (int s = NT / 2; s > 0; s >>= 1) { if (t < s) red[t] += red[t + s]; __syncthreads(); }
    if (t == 0) {
        float c = fmaxf(red[0] / (float)(N2 * D2), 1e-5f);
        float sw = 1.0f / c; g_sw[1] = sw; g_dq[1] = 1.0f / sw; s_sw2 = sw;
    }
    __syncthreads();
    red[t] = g_part3[t]; __syncthreads();
    for (int s = NT / 2; s > 0; s >>= 1) { if (t < s) red[t] += red[t + s]; __syncthreads(); }
    if (t == 0) {
        float c = fmaxf(red[0] / (float)(N3 * D3), 1e-5f);
        float sw = 1.0f / c; g_sw[2] = sw; g_dq[2] = 1.0f / sw; s_sw3 = sw;
    }
    __syncthreads();

    float sw2 = s_sw2, sw3 = s_sw3;
    for (int idx = t; idx < G2 * N2; idx += NT) {
        int g = idx / N2, j = idx % N2;
        const float* wp = w2 + j * D2 + 4 * g;
        int p = (qw(wp[0], sw2) & 0xff)
              | ((qw(wp[1], sw2) & 0xff) << 8)
              | ((qw(wp[2], sw2) & 0xff) << 16)
              | ((qw(wp[3], sw2) & 0xff) << 24);
        g_wq2[idx] = p;
    }
    for (int idx = t; idx < N3 * G3; idx += NT) {
        int j = idx / G3, g = idx % G3;
        const float* wp = w3 + j * D3 + 4 * g;
        int p = (qw(wp[0], sw3) & 0xff)
              | ((qw(wp[1], sw3) & 0xff) << 8)
              | ((qw(wp[2], sw3) & 0xff) << 16)
              | ((qw(wp[3], sw3) & 0xff) << 24);
        g_wq3[idx] = p;
    }
}

// ---------------- prep: quantize w1 (parallel) ----------------
__global__ void prep_quant_w1(const float* __restrict__ w1) {
    int idx = blockIdx.x * NT + threadIdx.x;
    if (idx >= G1 * N1) return;
    float sw = g_sw[0];
    int g = idx / N1, j = idx % N1;
    const float* wp = w1 + j * D1 + 4 * g;
    int p = (qw(wp[0], sw) & 0xff)
          | ((qw(wp[1], sw) & 0xff) << 8)
          | ((qw(wp[2], sw) & 0xff) << 16)
          | ((qw(wp[3], sw) & 0xff) << 24);
    g_wq1[idx] = p;
}

// ---------------- fused main kernel ----------------
__global__ __launch_bounds__(NT) void ffn_main(
    const float* __restrict__ x,
    const float* __restrict__ sc1,
    const float* __restrict__ sc2,
    const float* __restrict__ sc3,
    float* __restrict__ out)
{
    __shared__ int   s_xqT[G1][MTP];      // 28224 B  [k-group][token]
    __shared__ int   s_w[WCHUNK * N1];    //  8192 B
    __shared__ float s_scale1[D1];        //  3136 B
    __shared__ float s_scale2[D2];        //   512 B
    __shared__ float s_scale3[D3];        //   256 B
    __shared__ int   s_h1qT[G2][34];      //  4352 B  [k-group][token]
    __shared__ int   s_h2q[MT][G3];       //  2048 B
    __shared__ float s_c1[MT], s_c2[MT], s_c3[MT];

    const int t = threadIdx.x;
    const int warp = t >> 5, lane = t & 31;
    const float dq1 = g_dq[0], dq2 = g_dq[1], dq3 = g_dq[2];

    for (int i = t; i < D1; i += NT) s_scale1[i] = sc1[i];
    if (t < D2) s_scale2[t] = sc2[t];
    if (t < D3) s_scale3[t] = sc3[t];
    __syncthreads();

    // ---- phase 1: per-token RMSNorm + int8 absmax quant of x ----
    // Reference op order: t1 = x/(rms+eps); y = scale*t1; s = 127/clip(max|y|);
    // q = clip(round(y*s)).
    #pragma unroll 1
    for (int c = 0; c < 4; c++) {
        int ltok = warp * 4 + c;
        const float4* xr = (const float4*)(x + (size_t)(blockIdx.x * MT + ltok) * D1);
        float4 xv[7];
        float ssq = 0.f;
        #pragma unroll
        for (int i = 0; i < 7; i++) {
            int f = lane + 32 * i;
            xv[i] = make_float4(0.f, 0.f, 0.f, 0.f);
            if (f < G1) {
                float4 v = xr[f];
                xv[i] = v;
                ssq += v.x * v.x + v.y * v.y + v.z * v.z + v.w * v.w;
            }
        }
        #pragma unroll
        for (int m = 16; m > 0; m >>= 1)
            ssq += __shfl_xor_sync(0xffffffffu, ssq, m);
        float denom = sqrtf(ssq) * (1.0f / 28.0f) + 1e-8f;   // rms + eps

        float amx = 0.f;
        #pragma unroll
        for (int i = 0; i < 7; i++) {
            int f = lane + 32 * i;
            if (f < G1) {
                float4 sv = *(const float4*)(&s_scale1[4 * f]);
                float4 y;
                y.x = sv.x * (xv[i].x / denom);
                y.y = sv.y * (xv[i].y / denom);
                y.z = sv.z * (xv[i].z / denom);
                y.w = sv.w * (xv[i].w / denom);
                xv[i] = y;                       // keep y for quant pass
                amx = fmaxf(amx, fmaxf(fmaxf(fabsf(y.x), fabsf(y.y)),
                                       fmaxf(fabsf(y.z), fabsf(y.w))));
            }
        }
        #pragma unroll
        for (int m = 16; m > 0; m >>= 1)
            amx = fmaxf(amx, __shfl_xor_sync(0xffffffffu, amx, m));
        float amc = fmaxf(amx, 1e-5f);
        float s = 127.0f / amc;
        if (lane == 0) s_c1[ltok] = (1.0f / s) * dq1;
        #pragma unroll
        for (int i = 0; i < 7; i++) {
            int f = lane + 32 * i;
            if (f < G1) {
                float4 y = xv[i];
                int p = (qact(y.x * s) & 0xff)
                      | ((qact(y.y * s) & 0xff) << 8)
                      | ((qact(y.z * s) & 0xff) << 16)
                      | ((qact(y.w * s) & 0xff) << 24);
                s_xqT[f][ltok] = p;
            }
        }
    }
    __syncthreads();

    // ---- GEMM1: [32 x 128] = xq @ wq1^T ----
    // Each thread: 4 tokens (warp's group) x 4 outputs. Per k-group:
    // 1 broadcast LDS.128 (acts) + 1 LDS.128 (weights) feed 16 dp4a.
    const int tj = t & 31;          // output group: j = tj*4 .. +3
    const int wj = tj * 4;
    const int tg = warp;            // token group: tokens tg*4 .. +3

    int acc[4][4];
    #pragma unroll
    for (int c = 0; c < 4; c++)
        #pragma unroll
        for (int j = 0; j < 4; j++) acc[c][j] = 0;

    #pragma unroll 1
    for (int f0 = 0; f0 < 192; f0 += WCHUNK) {
        #pragma unroll
        for (int idx = t; idx < WCHUNK * 32; idx += NT)
            ((int4*)s_w)[idx] = ((const int4*)(g_wq1 + f0 * N1))[idx];
        __syncthreads();
        #pragma unroll
        for (int ff = 0; ff < WCHUNK; ff++) {
            int4 a = *(const int4*)&s_xqT[f0 + ff][tg * 4];
            int4 w = *(const int4*)(s_w + ff * N1 + wj);
            acc[0][0] = __dp4a(a.x, w.x, acc[0][0]); acc[0][1] = __dp4a(a.x, w.y, acc[0][1]);
            acc[0][2] = __dp4a(a.x, w.z, acc[0][2]); acc[0][3] = __dp4a(a.x, w.w, acc[0][3]);
            acc[1][0] = __dp4a(a.y, w.x, acc[1][0]); acc[1][1] = __dp4a(a.y, w.y, acc[1][1]);
            acc[1][2] = __dp4a(a.y, w.z, acc[1][2]); acc[1][3] = __dp4a(a.y, w.w, acc[1][3]);
            acc[2][0] = __dp4a(a.z, w.x, acc[2][0]); acc[2][1] = __dp4a(a.z, w.y, acc[2][1]);
            acc[2][2] = __dp4a(a.z, w.z, acc[2][2]); acc[2][3] = __dp4a(a.z, w.w, acc[2][3]);
            acc[3][0] = __dp4a(a.w, w.x, acc[3][0]); acc[3][1] = __dp4a(a.w, w.y, acc[3][1]);
            acc[3][2] = __dp4a(a.w, w.z, acc[3][2]); acc[3][3] = __dp4a(a.w, w.w, acc[3][3]);
        }
        __syncthreads();
    }
    {   // tail: k-groups 192..195
        if (t < 4 * 32)
            ((int4*)s_w)[t] = ((const int4*)(g_wq1 + 192 * N1))[t];
        __syncthreads();
        #pragma unroll
        for (int ff = 0; ff < 4; ff++) {
            int4 a = *(const int4*)&s_xqT[192 + ff][tg * 4];
            int4 w = *(const int4*)(s_w + ff * N1 + wj);
            acc[0][0] = __dp4a(a.x, w.x, acc[0][0]); acc[0][1] = __dp4a(a.x, w.y, acc[0][1]);
            acc[0][2] = __dp4a(a.x, w.z, acc[0][2]); acc[0][3] = __dp4a(a.x, w.w, acc[0][3]);
            acc[1][0] = __dp4a(a.y, w.x, acc[1][0]); acc[1][1] = __dp4a(a.y, w.y, acc[1][1]);
            acc[1][2] = __dp4a(a.y, w.z, acc[1][2]); acc[1][3] = __dp4a(a.y, w.w, acc[1][3]);
            acc[2][0] = __dp4a(a.z, w.x, acc[2][0]); acc[2][1] = __dp4a(a.z, w.y, acc[2][1]);
            acc[2][2] = __dp4a(a.z, w.z, acc[2][2]); acc[2][3] = __dp4a(a.z, w.w, acc[2][3]);
            acc[3][0] = __dp4a(a.w, w.x, acc[3][0]); acc[3][1] = __dp4a(a.w, w.y, acc[3][1]);
            acc[3][2] = __dp4a(a.w, w.z, acc[3][2]); acc[3][3] = __dp4a(a.w, w.w, acc[3][3]);
        }
    }

    // ---- epilogue 1: dequant, relu, RMSNorm(128) + quant (full-warp reduce) ----
    #pragma unroll
    for (int c = 0; c < 4; c++) {
        int tok = tg * 4 + c;
        float cf = s_c1[tok];
        float h[4];
        float ssq = 0.f;
        #pragma unroll
        for (int j = 0; j < 4; j++) {
            float v = fmaxf((float)acc[c][j] * cf, 0.f);
            h[j] = v;
            ssq += v * v;
        }
        #pragma unroll
        for (int m = 16; m > 0; m >>= 1)
            ssq += __shfl_xor_sync(0xffffffffu, ssq, m);
        float denom = sqrtf(ssq) * 0.08838834764831845f + 1e-8f;  // rms+eps, 1/sqrt(128)
        float amx = 0.f;
        #pragma unroll
        for (int j = 0; j < 4; j++) {
            float y = s_scale2[wj + j] * (h[j] / denom);
            h[j] = y;
            amx = fmaxf(amx, fabsf(y));
        }
        #pragma unroll
        for (int m = 16; m > 0; m >>= 1)
            amx = fmaxf(amx, __shfl_xor_sync(0xffffffffu, amx, m));
        float amc = fmaxf(amx, 1e-5f);
        float s = 127.0f / amc;
        if (lane == 0) s_c2[tok] = (1.0f / s) * dq2;
        int p = (qact(h[0] * s) & 0xff)
              | ((qact(h[1] * s) & 0xff) << 8)
              | ((qact(h[2] * s) & 0xff) << 16)
              | ((qact(h[3] * s) & 0xff) << 24);
        s_h1qT[tj][tok] = p;    // k-group of layer2 == tj
    }

    // stage w2 into s_w while epilogue writes settle
    __syncthreads();
    #pragma unroll
    for (int idx = t; idx < G2 * N2 / 4; idx += NT)
        ((int4*)s_w)[idx] = ((const int4*)g_wq2)[idx];
    __syncthreads();

    // ---- GEMM2: [32 x 64] = h1q @ wq2^T (thread: 2 tokens x 4 outputs) ----
    const int tj2 = t & 15;
    const int j2 = tj2 * 4;
    const int tm2 = t >> 4;        // token pair index 0..15
    int acc2[2][4];
    #pragma unroll
    for (int c = 0; c < 2; c++)
        #pragma unroll
        for (int j = 0; j < 4; j++) acc2[c][j] = 0;

    #pragma unroll 8
    for (int g = 0; g < G2; g++) {
        int2 a = *(const int2*)&s_h1qT[g][tm2 * 2];
        int4 w = *(const int4*)(s_w + g * N2 + j2);
        acc2[0][0] = __dp4a(a.x, w.x, acc2[0][0]); acc2[0][1] = __dp4a(a.x, w.y, acc2[0][1]);
        acc2[0][2] = __dp4a(a.x, w.z, acc2[0][2]); acc2[0][3] = __dp4a(a.x, w.w, acc2[0][3]);
        acc2[1][0] = __dp4a(a.y, w.x, acc2[1][0]); acc2[1][1] = __dp4a(a.y, w.y, acc2[1][1]);
        acc2[1][2] = __dp4a(a.y, w.z, acc2[1][2]); acc2[1][3] = __dp4a(a.y, w.w, acc2[1][3]);
    }

    // ---- epilogue 2: dequant, relu, RMSNorm(64) + quant (16-lane reduce) ----
    #pragma unroll
    for (int c = 0; c < 2; c++) {
        int tok = tm2 * 2 + c;
        float cf = s_c2[tok];
        float h[4];
        float ssq = 0.f;
        #pragma unroll
        for (int j = 0; j < 4; j++) {
            float v = fmaxf((float)acc2[c][j] * cf, 0.f);
            h[j] = v;
            ssq += v * v;
        }
        #pragma unroll
        for (int m = 1; m < 16; m <<= 1)
            ssq += __shfl_xor_sync(0xffffffffu, ssq, m);
        float denom = sqrtf(ssq) * 0.125f + 1e-8f;   // 1/sqrt(64)
        float amx = 0.f;
        #pragma unroll
        for (int j = 0; j < 4; j++) {
            float y = s_scale3[j2 + j] * (h[j] / denom);
            h[j] = y;
            amx = fmaxf(amx, fabsf(y));
        }
        #pragma unroll
        for (int m = 1; m < 16; m <<= 1)
            amx = fmaxf(amx, __shfl_xor_sync(0xffffffffu, amx, m));
        float amc = fmaxf(amx, 1e-5f);
        float s = 127.0f / amc;
        if (tj2 == 0) s_c3[tok] = (1.0f / s) * dq3;
        int p = (qact(h[0] * s) & 0xff)
              | ((qact(h[1] * s) & 0xff) << 8)
              | ((qact(h[2] * s) & 0xff) << 16)
              | ((qact(h[3] * s) & 0xff) << 24);
        s_h2q[tok][tj2] = p;     // k-group of layer3 == tj2
    }
    __syncthreads();

    // ---- GEMM3: [32 x 10] = h2q @ wq3^T, write output ----
    for (int p = t; p < MT * N3; p += NT) {
        int ltok = p / N3, j = p % N3;
        int a3 = 0;
        #pragma unroll
        for (int g = 0; g < G3; g++)
            a3 = __dp4a(s_h2q[ltok][g], g_wq3[j * G3 + g], a3);
        out[(blockIdx.x * MT + ltok) * N3 + j] = (float)a3 * s_c3[ltok];
    }
}

extern "C" void kernel_launch(void* const* d_in, const int* in_sizes, int n_in,
                              void* d_out, int out_size) {
    const float* x   = (const float*)d_in[0];
    const float* w1  = (const float*)d_in[1];
    const float* sc1 = (const float*)d_in[2];
    const float* w2  = (const float*)d_in[3];
    const float* sc2 = (const float*)d_in[4];
    const float* w3  = (const float*)d_in[5];
    const float* sc3 = (const float*)d_in[6];
    float* out = (float*)d_out;

    int ntok = in_sizes[0] / D1;   // 65536

    prep_partial<<<NPART, NT>>>(w1, w2, w3);
    prep_finalize<<<1, NT>>>(w2, w3);
    prep_quant_w1<<<(G1 * N1 + NT - 1) / NT, NT>>>(w1);
    ffn_main<<<ntok / MT, NT>>>(x, sc1, sc2, sc3, out);
}

// round 4
// speedup vs baseline: 1.7131x; 1.2063x over previous
#include <cuda_runtime.h>
#include <cstdint>

#define D1 784
#define G1 196   // D1/4
#define N1 128
#define D2 128
#define G2 32
#define N2 64
#define D3 64
#define G3 16
#define N3 10
#define MT 32    // tokens per block
#define NT 256
#define NPART 256
#define KC 25          // k32 chunks for layer1 (800 = 25*32, padded from 784)
#define XROW 204       // ints per token row in smem (816 B)
#define WROW 12        // ints per weight n-row per chunk (48 B)
#define WCHUNK_INTS (128 * WROW)   // 1536 ints = 6144 B per k-chunk

// Layer-1 weights prepacked in ldmatrix-fragment-friendly layout:
// [kc][n][12 ints] ; ints 0..7 = k bytes kc*32..+31 (zero beyond 783), 8..11 pad.
__device__ __align__(16) int g_wq1f[KC * WCHUNK_INTS];
__device__ __align__(16) int g_wq2[G2 * N2];   // [kgroup][j]
__device__ __align__(16) int g_wq3[N3 * G3];   // [j][kgroup]
__device__ float g_part1[NPART], g_part2[NPART], g_part3[NPART];
__device__ float g_sw[3];   // 1/clip(mean|w|,1e-5)
__device__ float g_dq[3];   // clip(mean|w|,1e-5)

__device__ __forceinline__ int qact(float v) {
    int q = __float2int_rn(v);
    return max(-128, min(127, q));
}
__device__ __forceinline__ int qw(float w, float s) {
    int q = __float2int_rn(w * s);
    return max(-1, min(1, q));
}
__device__ __forceinline__ uint32_t smem_u32(const void* p) {
    return (uint32_t)__cvta_generic_to_shared(p);
}
__device__ __forceinline__ void ldsm_x4(uint32_t addr, int& r0, int& r1, int& r2, int& r3) {
    asm volatile("ldmatrix.sync.aligned.m8n8.x4.shared.b16 {%0,%1,%2,%3}, [%4];\n"
                 : "=r"(r0), "=r"(r1), "=r"(r2), "=r"(r3) : "r"(addr));
}
__device__ __forceinline__ void imma16832(int* d, const int* a, const int* b) {
    asm volatile("mma.sync.aligned.m16n8k32.row.col.s32.s8.s8.s32 "
                 "{%0,%1,%2,%3}, {%4,%5,%6,%7}, {%8,%9}, {%0,%1,%2,%3};\n"
                 : "+r"(d[0]), "+r"(d[1]), "+r"(d[2]), "+r"(d[3])
                 : "r"(a[0]), "r"(a[1]), "r"(a[2]), "r"(a[3]), "r"(b[0]), "r"(b[1]));
}
#define CP16(dst, src) asm volatile("cp.async.cg.shared.global [%0], [%1], 16;\n" :: "r"(dst), "l"(src))
#define CP_COMMIT()    asm volatile("cp.async.commit_group;\n" ::: "memory")
#define CP_WAIT0()     asm volatile("cp.async.wait_group 0;\n" ::: "memory")

// ---------------- prep: deterministic mean(|w|) partials ----------------
__global__ void prep_partial(const float* __restrict__ w1,
                             const float* __restrict__ w2,
                             const float* __restrict__ w3) {
    __shared__ float red[NT];
    int t = threadIdx.x;
    int gid = blockIdx.x * NT + t;
    int stride = NPART * NT;
    float s1 = 0.f, s2 = 0.f, s3 = 0.f;
    for (int i = gid; i < N1 * D1; i += stride) s1 += fabsf(w1[i]);
    for (int i = gid; i < N2 * D2; i += stride) s2 += fabsf(w2[i]);
    for (int i = gid; i < N3 * D3; i += stride) s3 += fabsf(w3[i]);

    red[t] = s1; __syncthreads();
    for (int s = NT / 2; s > 0; s >>= 1) { if (t < s) red[t] += red[t + s]; __syncthreads(); }
    if (t == 0) g_part1[blockIdx.x] = red[0];
    __syncthreads();
    red[t] = s2; __syncthreads();
    for (int s = NT / 2; s > 0; s >>= 1) { if (t < s) red[t] += red[t + s]; __syncthreads(); }
    if (t == 0) g_part2[blockIdx.x] = red[0];
    __syncthreads();
    red[t] = s3; __syncthreads();
    for (int s = NT / 2; s > 0; s >>= 1) { if (t < s) red[t] += red[t + s]; __syncthreads(); }
    if (t == 0) g_part3[blockIdx.x] = red[0];
}

// ---------------- prep: finalize means, quantize w2/w3 ----------------
__global__ void prep_finalize(const float* __restrict__ w2,
                              const float* __restrict__ w3) {
    __shared__ float red[NT];
    __shared__ float s_sw2, s_sw3;
    int t = threadIdx.x;

    red[t] = g_part1[t]; __syncthreads();
    for (int s = NT / 2; s > 0; s >>= 1) { if (t < s) red[t] += red[t + s]; __syncthreads(); }
    if (t == 0) {
        float c = fmaxf(red[0] / (float)(N1 * D1), 1e-5f);
        float sw = 1.0f / c; g_sw[0] = sw; g_dq[0] = 1.0f / sw;
    }
    __syncthreads();
    red[t] = g_part2[t]; __syncthreads();
    for (int s = NT / 2; s > 0; s >>= 1) { if (t < s) red[t] += red[t + s]; __syncthreads(); }
    if (t == 0) {
        float c = fmaxf(red[0] / (float)(N2 * D2), 1e-5f);
        float sw = 1.0f / c; g_sw[1] = sw; g_dq[1] = 1.0f / sw; s_sw2 = sw;
    }
    __syncthreads();
    red[t] = g_part3[t]; __syncthreads();
    for (int s = NT / 2; s > 0; s >>= 1) { if (t < s) red[t] += red[t + s]; __syncthreads(); }
    if (t == 0) {
        float c = fmaxf(red[0] / (float)(N3 * D3), 1e-5f);
        float sw = 1.0f / c; g_sw[2] = sw; g_dq[2] = 1.0f / sw; s_sw3 = sw;
    }
    __syncthreads();

    float sw2 = s_sw2, sw3 = s_sw3;
    for (int idx = t; idx < G2 * N2; idx += NT) {
        int g = idx / N2, j = idx % N2;
        const float* wp = w2 + j * D2 + 4 * g;
        int p = (qw(wp[0], sw2) & 0xff)
              | ((qw(wp[1], sw2) & 0xff) << 8)
              | ((qw(wp[2], sw2) & 0xff) << 16)
              | ((qw(wp[3], sw2) & 0xff) << 24);
        g_wq2[idx] = p;
    }
    for (int idx = t; idx < N3 * G3; idx += NT) {
        int j = idx / G3, g = idx % G3;
        const float* wp = w3 + j * D3 + 4 * g;
        int p = (qw(wp[0], sw3) & 0xff)
              | ((qw(wp[1], sw3) & 0xff) << 8)
              | ((qw(wp[2], sw3) & 0xff) << 16)
              | ((qw(wp[3], sw3) & 0xff) << 24);
        g_wq3[idx] = p;
    }
}

// ---------------- prep: quantize + fragment-pack w1 ----------------
__global__ void prep_quant_w1(const float* __restrict__ w1) {
    int idx = blockIdx.x * NT + threadIdx.x;     // over [kc][n][i]
    if (idx >= KC * 128 * WROW) return;
    float sw = g_sw[0];
    int kc = idx / (128 * WROW);
    int r  = idx % (128 * WROW);
    int n  = r / WROW;
    int i  = r % WROW;
    int p = 0;
    if (i < 8) {
        int k0 = kc * 32 + i * 4;
        #pragma unroll
        for (int b = 0; b < 4; b++) {
            int k = k0 + b;
            int q = (k < D1) ? qw(w1[n * D1 + k], sw) : 0;
            p |= (q & 0xff) << (8 * b);
        }
    }
    g_wq1f[idx] = p;
}

// ---------------- fused main kernel ----------------
__global__ __launch_bounds__(NT) void ffn_main(
    const float* __restrict__ x,
    const float* __restrict__ sc1,
    const float* __restrict__ sc2,
    const float* __restrict__ sc3,
    float* __restrict__ out)
{
    // Region A: xq [32][204] ints (26112 B); reused as h1 f32 [32][132] (16896 B)
    __shared__ __align__(16) char s_regionA[MT * XROW * 4];
    // Region B: w1 double buffer 2*6144 B; reused as h1qT [32][34] + h2q [32][16]
    __shared__ __align__(16) char s_regionB[2 * WCHUNK_INTS * 4];
    __shared__ float s_scale1[D1];
    __shared__ float s_scale2[D2];
    __shared__ float s_scale3[D3];
    __shared__ float s_c1[MT], s_c2[MT], s_c3[MT];

    int* s_xq   = (int*)s_regionA;               // [tok][XROW]
    float* s_h1 = (float*)s_regionA;             // [tok][132]
    int* s_h1qT = (int*)s_regionB;               // [G2][34]
    int* s_h2q  = (int*)(s_regionB + G2 * 34 * 4); // [MT][G3]

    const int t = threadIdx.x;
    const int warp = t >> 5, lane = t & 31;
    const float dq1 = g_dq[0], dq2 = g_dq[1], dq3 = g_dq[2];

    // prefetch weight chunk 0 (overlaps with phase 1)
    {
        const int4* src = (const int4*)g_wq1f;
        uint32_t dst = smem_u32(s_regionB);
        CP16(dst + (uint32_t)t * 16, (const void*)(src + t));
        if (t + NT < WCHUNK_INTS / 4) CP16(dst + (uint32_t)(t + NT) * 16, (const void*)(src + t + NT));
        CP_COMMIT();
    }

    for (int i = t; i < D1; i += NT) s_scale1[i] = sc1[i];
    if (t < D2) s_scale2[t] = sc2[t];
    if (t < D3) s_scale3[t] = sc3[t];
    // zero the k-padding ints (f = 196..203) of every token row
    {
        int tok = t >> 3, f = G1 + (t & 7);
        s_xq[tok * XROW + f] = 0;
    }
    __syncthreads();   // scales + padding visible before phase 1 reads them (R3 race fix)

    // ---- phase 1: per-token RMSNorm + int8 absmax quant of x (ref op order) ----
    #pragma unroll 1
    for (int c = 0; c < 4; c++) {
        int ltok = warp * 4 + c;
        const float4* xr = (const float4*)(x + (size_t)(blockIdx.x * MT + ltok) * D1);
        float4 xv[7];
        float ssq = 0.f;
        #pragma unroll
        for (int i = 0; i < 7; i++) {
            int f = lane + 32 * i;
            xv[i] = make_float4(0.f, 0.f, 0.f, 0.f);
            if (f < G1) {
                float4 v = xr[f];
                xv[i] = v;
                ssq += v.x * v.x + v.y * v.y + v.z * v.z + v.w * v.w;
            }
        }
        #pragma unroll
        for (int m = 16; m > 0; m >>= 1)
            ssq += __shfl_xor_sync(0xffffffffu, ssq, m);
        float denom = sqrtf(ssq) * (1.0f / 28.0f) + 1e-8f;

        float amx = 0.f;
        #pragma unroll
        for (int i = 0; i < 7; i++) {
            int f = lane + 32 * i;
            if (f < G1) {
                float4 sv = *(const float4*)(&s_scale1[4 * f]);
                float4 y;
                y.x = sv.x * (xv[i].x / denom);
                y.y = sv.y * (xv[i].y / denom);
                y.z = sv.z * (xv[i].z / denom);
                y.w = sv.w * (xv[i].w / denom);
                xv[i] = y;
                amx = fmaxf(amx, fmaxf(fmaxf(fabsf(y.x), fabsf(y.y)),
                                       fmaxf(fabsf(y.z), fabsf(y.w))));
            }
        }
        #pragma unroll
        for (int m = 16; m > 0; m >>= 1)
            amx = fmaxf(amx, __shfl_xor_sync(0xffffffffu, amx, m));
        float amc = fmaxf(amx, 1e-5f);
        float s = 127.0f / amc;
        if (lane == 0) s_c1[ltok] = (1.0f / s) * dq1;
        #pragma unroll
        for (int i = 0; i < 7; i++) {
            int f = lane + 32 * i;
            if (f < G1) {
                float4 y = xv[i];
                int p = (qact(y.x * s) & 0xff)
                      | ((qact(y.y * s) & 0xff) << 8)
                      | ((qact(y.z * s) & 0xff) << 16)
                      | ((qact(y.w * s) & 0xff) << 24);
                s_xq[ltok * XROW + f] = p;
            }
        }
    }

    // ---- GEMM1: [32 x 128] IMMA, K=800 in 25 chunks, double-buffered weights ----
    const int mt = warp >> 2;      // m-tile (16 tokens)
    const int ng = warp & 3;       // n-group (32 outputs)

    int acc[4][4];
    #pragma unroll
    for (int i = 0; i < 4; i++)
        #pragma unroll
        for (int j = 0; j < 4; j++) acc[i][j] = 0;

    // ldmatrix lane addressing
    const int gA = lane >> 3, iA = lane & 7;
    const int a_row = mt * 16 + (((gA == 1) || (gA == 3)) ? 8 : 0) + iA;
    const uint32_t a_base = smem_u32(s_xq + a_row * XROW) + ((gA >= 2) ? 16u : 0u);
    const int b_rowoff = ((gA >= 2) ? 8 : 0) + iA;
    const uint32_t b_base = smem_u32(s_regionB) + (uint32_t)(ng * 32 + b_rowoff) * 48u
                          + (uint32_t)((gA & 1) * 16);

    #pragma unroll 1
    for (int kc = 0; kc < KC; kc++) {
        CP_WAIT0();
        __syncthreads();
        if (kc + 1 < KC) {
            const int4* src = (const int4*)(g_wq1f + (kc + 1) * WCHUNK_INTS);
            uint32_t dst = smem_u32(s_regionB) + (uint32_t)(((kc + 1) & 1) * WCHUNK_INTS * 4);
            CP16(dst + (uint32_t)t * 16, (const void*)(src + t));
            if (t + NT < WCHUNK_INTS / 4)
                CP16(dst + (uint32_t)(t + NT) * 16, (const void*)(src + t + NT));
            CP_COMMIT();
        }
        int a[4];
        ldsm_x4(a_base + (uint32_t)kc * 32u, a[0], a[1], a[2], a[3]);
        uint32_t bb = b_base + (uint32_t)((kc & 1) * WCHUNK_INTS * 4);
        int b0[4], b1[4];
        ldsm_x4(bb,        b0[0], b0[1], b0[2], b0[3]);   // n-tiles 0,1
        ldsm_x4(bb + 768u, b1[0], b1[1], b1[2], b1[3]);   // n-tiles 2,3
        imma16832(acc[0], a, b0);
        imma16832(acc[1], a, b0 + 2);
        imma16832(acc[2], a, b1);
        imma16832(acc[3], a, b1 + 2);
    }
    __syncthreads();   // all ldmatrix reads of regionA/B done; safe to reuse

    // scatter relu(acc * c1) as f32 into region A  (h1[tok][132])
    {
        int r_lo = mt * 16 + (lane >> 2);
        float c1lo = s_c1[r_lo];
        float c1hi = s_c1[r_lo + 8];
        #pragma unroll
        for (int nt = 0; nt < 4; nt++) {
            int j = ng * 32 + nt * 8 + 2 * (lane & 3);
            float2 vlo, vhi;
            vlo.x = fmaxf((float)acc[nt][0] * c1lo, 0.f);
            vlo.y = fmaxf((float)acc[nt][1] * c1lo, 0.f);
            vhi.x = fmaxf((float)acc[nt][2] * c1hi, 0.f);
            vhi.y = fmaxf((float)acc[nt][3] * c1hi, 0.f);
            *(float2*)&s_h1[r_lo * 132 + j] = vlo;
            *(float2*)&s_h1[(r_lo + 8) * 132 + j] = vhi;
        }
    }
    __syncthreads();

    // ---- epilogue 1: RMSNorm(128) + quant (warp per 4 tokens; R2-identical order) ----
    #pragma unroll 1
    for (int c = 0; c < 4; c++) {
        int tok = warp * 4 + c;
        float4 hv = *(const float4*)&s_h1[tok * 132 + 4 * lane];
        float ssq = hv.x * hv.x + hv.y * hv.y + hv.z * hv.z + hv.w * hv.w;
        #pragma unroll
        for (int m = 16; m > 0; m >>= 1)
            ssq += __shfl_xor_sync(0xffffffffu, ssq, m);
        float denom = sqrtf(ssq) * 0.08838834764831845f + 1e-8f;
        float4 sv = *(const float4*)&s_scale2[4 * lane];
        float4 y;
        y.x = sv.x * (hv.x / denom);
        y.y = sv.y * (hv.y / denom);
        y.z = sv.z * (hv.z / denom);
        y.w = sv.w * (hv.w / denom);
        float amx = fmaxf(fmaxf(fabsf(y.x), fabsf(y.y)), fmaxf(fabsf(y.z), fabsf(y.w)));
        #pragma unroll
        for (int m = 16; m > 0; m >>= 1)
            amx = fmaxf(amx, __shfl_xor_sync(0xffffffffu, amx, m));
        float amc = fmaxf(amx, 1e-5f);
        float s = 127.0f / amc;
        if (lane == 0) s_c2[tok] = (1.0f / s) * dq2;
        int p = (qact(y.x * s) & 0xff)
              | ((qact(y.y * s) & 0xff) << 8)
              | ((qact(y.z * s) & 0xff) << 16)
              | ((qact(y.w * s) & 0xff) << 24);
        s_h1qT[lane * 34 + tok] = p;   // k-group of layer2 == lane
    }
    __syncthreads();

    // ---- GEMM2: [32 x 64] dp4a (weights via L1/L2) ----
    const int tj2 = t & 15;
    const int j2 = tj2 * 4;
    const int tm2 = t >> 4;
    int acc2[2][4];
    #pragma unroll
    for (int c = 0; c < 2; c++)
        #pragma unroll
        for (int j = 0; j < 4; j++) acc2[c][j] = 0;

    #pragma unroll 8
    for (int g = 0; g < G2; g++) {
        int2 a = *(const int2*)&s_h1qT[g * 34 + tm2 * 2];
        int4 w = *(const int4*)(g_wq2 + g * N2 + j2);
        acc2[0][0] = __dp4a(a.x, w.x, acc2[0][0]); acc2[0][1] = __dp4a(a.x, w.y, acc2[0][1]);
        acc2[0][2] = __dp4a(a.x, w.z, acc2[0][2]); acc2[0][3] = __dp4a(a.x, w.w, acc2[0][3]);
        acc2[1][0] = __dp4a(a.y, w.x, acc2[1][0]); acc2[1][1] = __dp4a(a.y, w.y, acc2[1][1]);
        acc2[1][2] = __dp4a(a.y, w.z, acc2[1][2]); acc2[1][3] = __dp4a(a.y, w.w, acc2[1][3]);
    }

    // ---- epilogue 2: RMSNorm(64) + quant (16-lane reduce; R2-identical) ----
    #pragma unroll
    for (int c = 0; c < 2; c++) {
        int tok = tm2 * 2 + c;
        float cf = s_c2[tok];
        float h[4];
        float ssq = 0.f;
        #pragma unroll
        for (int j = 0; j < 4; j++) {
            float v = fmaxf((float)acc2[c][j] * cf, 0.f);
            h[j] = v;
            ssq += v * v;
        }
        #pragma unroll
        for (int m = 1; m < 16; m <<= 1)
            ssq += __shfl_xor_sync(0xffffffffu, ssq, m);
        float denom = sqrtf(ssq) * 0.125f + 1e-8f;
        float amx = 0.f;
        #pragma unroll
        for (int j = 0; j < 4; j++) {
            float y = s_scale3[j2 + j] * (h[j] / denom);
            h[j] = y;
            amx = fmaxf(amx, fabsf(y));
        }
        #pragma unroll
        for (int m = 1; m < 16; m <<= 1)
            amx = fmaxf(amx, __shfl_xor_sync(0xffffffffu, amx, m));
        float amc = fmaxf(amx, 1e-5f);
        float s = 127.0f / amc;
        if (tj2 == 0) s_c3[tok] = (1.0f / s) * dq3;
        int p = (qact(h[0] * s) & 0xff)
              | ((qact(h[1] * s) & 0xff) << 8)
              | ((qact(h[2] * s) & 0xff) << 16)
              | ((qact(h[3] * s) & 0xff) << 24);
        s_h2q[tok * G3 + tj2] = p;
    }
    __syncthreads();

    // ---- GEMM3: [32 x 10], write output ----
    for (int p = t; p < MT * N3; p += NT) {
        int ltok = p / N3, j = p % N3;
        int a3 = 0;
        #pragma unroll
        for (int g = 0; g < G3; g++)
            a3 = __dp4a(s_h2q[ltok * G3 + g], g_wq3[j * G3 + g], a3);
        out[(blockIdx.x * MT + ltok) * N3 + j] = (float)a3 * s_c3[ltok];
    }
}

extern "C" void kernel_launch(void* const* d_in, const int* in_sizes, int n_in,
                              void* d_out, int out_size) {
    const float* x   = (const float*)d_in[0];
    const float* w1  = (const float*)d_in[1];
    const float* sc1 = (const float*)d_in[2];
    const float* w2  = (const float*)d_in[3];
    const float* sc2 = (const float*)d_in[4];
    const float* w3  = (const float*)d_in[5];
    const float* sc3 = (const float*)d_in[6];
    float* out = (float*)d_out;

    int ntok = in_sizes[0] / D1;   // 65536

    prep_partial<<<NPART, NT>>>(w1, w2, w3);
    prep_finalize<<<1, NT>>>(w2, w3);
    prep_quant_w1<<<(KC * 128 * WROW + NT - 1) / NT, NT>>>(w1);
    ffn_main<<<ntok / MT, NT>>>(x, sc1, sc2, sc3, out);
}

// round 9
// speedup vs baseline: 1.8553x; 1.0830x over previous
#include <cuda_runtime.h>
#include <cstdint>

#define D1 784
#define G1 196   // D1/4
#define N1 128
#define D2 128
#define G2 32
#define N2 64
#define D3 64
#define G3 16
#define N3 10
#define MT 32    // tokens per block
#define NT 256
#define NPART 256
#define KC 25          // k32 chunks for layer1 (800 = 25*32, padded from 784)
#define XROW 204       // ints per token row in smem (816 B)
#define NTILES 16      // n8 tiles in N1=128

// Layer-1 weights prepacked in EXACT m16n8k32 B-fragment order:
// [kc][ntile][lane] -> int2 {b0,b1};  b_r byte i = w1q[n = nt*8 + lane/4]
// [k = kc*32 + r*16 + (lane%4)*4 + i]  (zero for k >= 784).
__device__ __align__(16) int g_wq1frag[KC * NTILES * 32 * 2];
__device__ __align__(16) int g_wq2[G2 * N2];   // [kgroup][j]
__device__ __align__(16) int g_wq3[N3 * G3];   // [j][kgroup]
__device__ float g_part1[NPART], g_part2[NPART], g_part3[NPART];
__device__ float g_sw[3];   // 1/clip(mean|w|,1e-5)
__device__ float g_dq[3];   // clip(mean|w|,1e-5)

__device__ __forceinline__ int qact(float v) {
    int q = __float2int_rn(v);
    return max(-128, min(127, q));
}
__device__ __forceinline__ int qw(float w, float s) {
    int q = __float2int_rn(w * s);
    return max(-1, min(1, q));
}
__device__ __forceinline__ uint32_t smem_u32(const void* p) {
    return (uint32_t)__cvta_generic_to_shared(p);
}
__device__ __forceinline__ void ldsm_x4(uint32_t addr, int& r0, int& r1, int& r2, int& r3) {
    asm volatile("ldmatrix.sync.aligned.m8n8.x4.shared.b16 {%0,%1,%2,%3}, [%4];\n"
                 : "=r"(r0), "=r"(r1), "=r"(r2), "=r"(r3) : "r"(addr));
}
__device__ __forceinline__ void imma16832(int* d, const int* a, const int* b) {
    asm volatile("mma.sync.aligned.m16n8k32.row.col.s32.s8.s8.s32 "
                 "{%0,%1,%2,%3}, {%4,%5,%6,%7}, {%8,%9}, {%0,%1,%2,%3};\n"
                 : "+r"(d[0]), "+r"(d[1]), "+r"(d[2]), "+r"(d[3])
                 : "r"(a[0]), "r"(a[1]), "r"(a[2]), "r"(a[3]), "r"(b[0]), "r"(b[1]));
}

// ---------------- prep: deterministic mean(|w|) partials ----------------
__global__ void prep_partial(const float* __restrict__ w1,
                             const float* __restrict__ w2,
                             const float* __restrict__ w3) {
    __shared__ float red[NT];
    int t = threadIdx.x;
    int gid = blockIdx.x * NT + t;
    int stride = NPART * NT;
    float s1 = 0.f, s2 = 0.f, s3 = 0.f;
    for (int i = gid; i < N1 * D1; i += stride) s1 += fabsf(w1[i]);
    for (int i = gid; i < N2 * D2; i += stride) s2 += fabsf(w2[i]);
    for (int i = gid; i < N3 * D3; i += stride) s3 += fabsf(w3[i]);

    red[t] = s1; __syncthreads();
    for (int s = NT / 2; s > 0; s >>= 1) { if (t < s) red[t] += red[t + s]; __syncthreads(); }
    if (t == 0) g_part1[blockIdx.x] = red[0];
    __syncthreads();
    red[t] = s2; __syncthreads();
    for (int s = NT / 2; s > 0; s >>= 1) { if (t < s) red[t] += red[t + s]; __syncthreads(); }
    if (t == 0) g_part2[blockIdx.x] = red[0];
    __syncthreads();
    red[t] = s3; __syncthreads();
    for (int s = NT / 2; s > 0; s >>= 1) { if (t < s) red[t] += red[t + s]; __syncthreads(); }
    if (t == 0) g_part3[blockIdx.x] = red[0];
}

// ---------------- prep: finalize means, quantize w2/w3 ----------------
__global__ void prep_finalize(const float* __restrict__ w2,
                              const float* __restrict__ w3) {
    __shared__ float red[NT];
    __shared__ float s_sw2, s_sw3;
    int t = threadIdx.x;

    red[t] = g_part1[t]; __syncthreads();
    for (int s = NT / 2; s > 0; s >>= 1) { if (t < s) red[t] += red[t + s]; __syncthreads(); }
    if (t == 0) {
        float c = fmaxf(red[0] / (float)(N1 * D1), 1e-5f);
        float sw = 1.0f / c; g_sw[0] = sw; g_dq[0] = 1.0f / sw;
    }
    __syncthreads();
    red[t] = g_part2[t]; __syncthreads();
    for (int s = NT / 2; s > 0; s >>= 1) { if (t < s) red[t] += red[t + s]; __syncthreads(); }
    if (t == 0) {
        float c = fmaxf(red[0] / (float)(N2 * D2), 1e-5f);
        float sw = 1.0f / c; g_sw[1] = sw; g_dq[1] = 1.0f / sw; s_sw2 = sw;
    }
    __syncthreads();
    red[t] = g_part3[t]; __syncthreads();
    for (int s = NT / 2; s > 0; s >>= 1) { if (t < s) red[t] += red[t + s]; __syncthreads(); }
    if (t == 0) {
        float c = fmaxf(red[0] / (float)(N3 * D3), 1e-5f);
        float sw = 1.0f / c; g_sw[2] = sw; g_dq[2] = 1.0f / sw; s_sw3 = sw;
    }
    __syncthreads();

    float sw2 = s_sw2, sw3 = s_sw3;
    for (int idx = t; idx < G2 * N2; idx += NT) {
        int g = idx / N2, j = idx % N2;
        const float* wp = w2 + j * D2 + 4 * g;
        int p = (qw(wp[0], sw2) & 0xff)
              | ((qw(wp[1], sw2) & 0xff) << 8)
              | ((qw(wp[2], sw2) & 0xff) << 16)
              | ((qw(wp[3], sw2) & 0xff) << 24);
        g_wq2[idx] = p;
    }
    for (int idx = t; idx < N3 * G3; idx += NT) {
        int j = idx / G3, g = idx % G3;
        const float* wp = w3 + j * D3 + 4 * g;
        int p = (qw(wp[0], sw3) & 0xff)
              | ((qw(wp[1], sw3) & 0xff) << 8)
              | ((qw(wp[2], sw3) & 0xff) << 16)
              | ((qw(wp[3], sw3) & 0xff) << 24);
        g_wq3[idx] = p;
    }
}

// ---------------- prep: quantize w1 into IMMA B-fragment order ----------------
__global__ void prep_quant_w1(const float* __restrict__ w1) {
    int idx = blockIdx.x * NT + threadIdx.x;     // one int per thread
    if (idx >= KC * NTILES * 32 * 2) return;
    float sw = g_sw[0];
    int kc   = idx >> 10;             // 1024 ints per k-chunk
    int rem  = idx & 1023;
    int nt   = rem >> 6;              // n-tile (16 per chunk)
    int lane = (rem >> 1) & 31;
    int r    = idx & 1;               // b0 / b1
    int n    = nt * 8 + (lane >> 2);
    int k0   = kc * 32 + r * 16 + (lane & 3) * 4;
    int p = 0;
    #pragma unroll
    for (int b = 0; b < 4; b++) {
        int k = k0 + b;
        int q = (k < D1) ? qw(w1[n * D1 + k], sw) : 0;
        p |= (q & 0xff) << (8 * b);
    }
    g_wq1frag[idx] = p;
}

// ---------------- fused main kernel ----------------
__global__ __launch_bounds__(NT) void ffn_main(
    const float* __restrict__ x,
    const float* __restrict__ sc1,
    const float* __restrict__ sc2,
    const float* __restrict__ sc3,
    float* __restrict__ out)
{
    // Region A: xq [32][204] ints (26112 B); reused as h1 f32 [32][132] (16896 B)
    __shared__ __align__(16) char s_regionA[MT * XROW * 4];
    __shared__ float s_scale1[D1];
    __shared__ float s_scale2[D2];
    __shared__ float s_scale3[D3];
    __shared__ __align__(16) int s_h1qT[G2 * 34];   // [kgroup][token]
    __shared__ __align__(16) int s_h2q[MT * G3];
    __shared__ float s_c1[MT], s_c2[MT], s_c3[MT];

    int* s_xq   = (int*)s_regionA;               // [tok][XROW]
    float* s_h1 = (float*)s_regionA;             // [tok][132]

    const int t = threadIdx.x;
    const int warp = t >> 5, lane = t & 31;
    const float dq1 = g_dq[0], dq2 = g_dq[1], dq3 = g_dq[2];

    for (int i = t; i < D1; i += NT) s_scale1[i] = sc1[i];
    if (t < D2) s_scale2[t] = sc2[t];
    if (t < D3) s_scale3[t] = sc3[t];
    // zero the k-padding ints (f = 196..203) of every token row
    {
        int tok = t >> 3, f = G1 + (t & 7);
        s_xq[tok * XROW + f] = 0;
    }
    __syncthreads();   // scales + padding visible before phase 1 reads them

    // ---- phase 1: per-token RMSNorm + int8 absmax quant of x (ref op order) ----
    #pragma unroll 1
    for (int c = 0; c < 4; c++) {
        int ltok = warp * 4 + c;
        const float4* xr = (const float4*)(x + (size_t)(blockIdx.x * MT + ltok) * D1);
        float4 xv[7];
        float ssq = 0.f;
        #pragma unroll
        for (int i = 0; i < 7; i++) {
            int f = lane + 32 * i;
            xv[i] = make_float4(0.f, 0.f, 0.f, 0.f);
            if (f < G1) {
                float4 v = xr[f];
                xv[i] = v;
                ssq += v.x * v.x + v.y * v.y + v.z * v.z + v.w * v.w;
            }
        }
        #pragma unroll
        for (int m = 16; m > 0; m >>= 1)
            ssq += __shfl_xor_sync(0xffffffffu, ssq, m);
        float denom = sqrtf(ssq) * (1.0f / 28.0f) + 1e-8f;

        float amx = 0.f;
        #pragma unroll
        for (int i = 0; i < 7; i++) {
            int f = lane + 32 * i;
            if (f < G1) {
                float4 sv = *(const float4*)(&s_scale1[4 * f]);
                float4 y;
                y.x = sv.x * (xv[i].x / denom);
                y.y = sv.y * (xv[i].y / denom);
                y.z = sv.z * (xv[i].z / denom);
                y.w = sv.w * (xv[i].w / denom);
                xv[i] = y;
                amx = fmaxf(amx, fmaxf(fmaxf(fabsf(y.x), fabsf(y.y)),
                                       fmaxf(fabsf(y.z), fabsf(y.w))));
            }
        }
        #pragma unroll
        for (int m = 16; m > 0; m >>= 1)
            amx = fmaxf(amx, __shfl_xor_sync(0xffffffffu, amx, m));
        float amc = fmaxf(amx, 1e-5f);
        float s = 127.0f / amc;
        if (lane == 0) s_c1[ltok] = (1.0f / s) * dq1;
        #pragma unroll
        for (int i = 0; i < 7; i++) {
            int f = lane + 32 * i;
            if (f < G1) {
                float4 y = xv[i];
                int p = (qact(y.x * s) & 0xff)
                      | ((qact(y.y * s) & 0xff) << 8)
                      | ((qact(y.z * s) & 0xff) << 16)
                      | ((qact(y.w * s) & 0xff) << 24);
                s_xq[ltok * XROW + f] = p;
            }
        }
    }
    __syncthreads();   // xq complete before cross-warp ldmatrix reads

    // ---- GEMM1: [32 x 128] IMMA; A via ldmatrix (smem), B via LDG fragments ----
    const int mt = warp >> 2;      // m-tile (16 tokens)
    const int ng = warp & 3;       // n-group (4 n-tiles = 32 outputs)

    int acc[4][4];
    #pragma unroll
    for (int i = 0; i < 4; i++)
        #pragma unroll
        for (int j = 0; j < 4; j++) acc[i][j] = 0;

    // A ldmatrix lane addressing (unchanged from R4)
    const int gA = lane >> 3, iA = lane & 7;
    const int a_row = mt * 16 + (((gA == 1) || (gA == 3)) ? 8 : 0) + iA;
    const uint32_t a_base = smem_u32(s_xq + a_row * XROW) + ((gA >= 2) ? 16u : 0u);

    // B fragment pointer: [kc][nt][lane] int2; this warp's first n-tile = ng*4
    const int2* bfr = ((const int2*)g_wq1frag) + (ng * 4) * 32 + lane;

    #pragma unroll 5
    for (int kc = 0; kc < KC; kc++) {
        int a[4];
        ldsm_x4(a_base + (uint32_t)kc * 32u, a[0], a[1], a[2], a[3]);
        const int2* bk = bfr + kc * (NTILES * 32);
        int2 b0 = __ldg(bk);
        int2 b1 = __ldg(bk + 32);
        int2 b2 = __ldg(bk + 64);
        int2 b3 = __ldg(bk + 96);
        imma16832(acc[0], a, (const int*)&b0);
        imma16832(acc[1], a, (const int*)&b1);
        imma16832(acc[2], a, (const int*)&b2);
        imma16832(acc[3], a, (const int*)&b3);
    }
    __syncthreads();   // all ldmatrix reads of regionA done; safe to reuse

    // scatter relu(acc * c1) as f32 into region A  (h1[tok][132])
    {
        int r_lo = mt * 16 + (lane >> 2);
        float c1lo = s_c1[r_lo];
        float c1hi = s_c1[r_lo + 8];
        #pragma unroll
        for (int nt = 0; nt < 4; nt++) {
            int j = ng * 32 + nt * 8 + 2 * (lane & 3);
            float2 vlo, vhi;
            vlo.x = fmaxf((float)acc[nt][0] * c1lo, 0.f);
            vlo.y = fmaxf((float)acc[nt][1] * c1lo, 0.f);
            vhi.x = fmaxf((float)acc[nt][2] * c1hi, 0.f);
            vhi.y = fmaxf((float)acc[nt][3] * c1hi, 0.f);
            *(float2*)&s_h1[r_lo * 132 + j] = vlo;
            *(float2*)&s_h1[(r_lo + 8) * 132 + j] = vhi;
        }
    }
    __syncthreads();

    // ---- epilogue 1: RMSNorm(128) + quant (warp per 4 tokens; R4-identical) ----
    #pragma unroll 1
    for (int c = 0; c < 4; c++) {
        int tok = warp * 4 + c;
        float4 hv = *(const float4*)&s_h1[tok * 132 + 4 * lane];
        float ssq = hv.x * hv.x + hv.y * hv.y + hv.z * hv.z + hv.w * hv.w;
        #pragma unroll
        for (int m = 16; m > 0; m >>= 1)
            ssq += __shfl_xor_sync(0xffffffffu, ssq, m);
        float denom = sqrtf(ssq) * 0.08838834764831845f + 1e-8f;
        float4 sv = *(const float4*)&s_scale2[4 * lane];
        float4 y;
        y.x = sv.x * (hv.x / denom);
        y.y = sv.y * (hv.y / denom);
        y.z = sv.z * (hv.z / denom);
        y.w = sv.w * (hv.w / denom);
        float amx = fmaxf(fmaxf(fabsf(y.x), fabsf(y.y)), fmaxf(fabsf(y.z), fabsf(y.w)));
        #pragma unroll
        for (int m = 16; m > 0; m >>= 1)
            amx = fmaxf(amx, __shfl_xor_sync(0xffffffffu, amx, m));
        float amc = fmaxf(amx, 1e-5f);
        float s = 127.0f / amc;
        if (lane == 0) s_c2[tok] = (1.0f / s) * dq2;
        int p = (qact(y.x * s) & 0xff)
              | ((qact(y.y * s) & 0xff) << 8)
              | ((qact(y.z * s) & 0xff) << 16)
              | ((qact(y.w * s) & 0xff) << 24);
        s_h1qT[lane * 34 + tok] = p;   // k-group of layer2 == lane
    }
    __syncthreads();

    // ---- GEMM2: [32 x 64] dp4a (weights via L1/L2) ----
    const int tj2 = t & 15;
    const int j2 = tj2 * 4;
    const int tm2 = t >> 4;
    int acc2[2][4];
    #pragma unroll
    for (int c = 0; c < 2; c++)
        #pragma unroll
        for (int j = 0; j < 4; j++) acc2[c][j] = 0;

    #pragma unroll 8
    for (int g = 0; g < G2; g++) {
        int2 a = *(const int2*)&s_h1qT[g * 34 + tm2 * 2];
        int4 w = *(const int4*)(g_wq2 + g * N2 + j2);
        acc2[0][0] = __dp4a(a.x, w.x, acc2[0][0]); acc2[0][1] = __dp4a(a.x, w.y, acc2[0][1]);
        acc2[0][2] = __dp4a(a.x, w.z, acc2[0][2]); acc2[0][3] = __dp4a(a.x, w.w, acc2[0][3]);
        acc2[1][0] = __dp4a(a.y, w.x, acc2[1][0]); acc2[1][1] = __dp4a(a.y, w.y, acc2[1][1]);
        acc2[1][2] = __dp4a(a.y, w.z, acc2[1][2]); acc2[1][3] = __dp4a(a.y, w.w, acc2[1][3]);
    }

    // ---- epilogue 2: RMSNorm(64) + quant (16-lane reduce; R4-identical) ----
    #pragma unroll
    for (int c = 0; c < 2; c++) {
        int tok = tm2 * 2 + c;
        float cf = s_c2[tok];
        float h[4];
        float ssq = 0.f;
        #pragma unroll
        for (int j = 0; j < 4; j++) {
            float v = fmaxf((float)acc2[c][j] * cf, 0.f);
            h[j] = v;
            ssq += v * v;
        }
        #pragma unroll
        for (int m = 1; m < 16; m <<= 1)
            ssq += __shfl_xor_sync(0xffffffffu, ssq, m);
        float denom = sqrtf(ssq) * 0.125f + 1e-8f;
        float amx = 0.f;
        #pragma unroll
        for (int j = 0; j < 4; j++) {
            float y = s_scale3[j2 + j] * (h[j] / denom);
            h[j] = y;
            amx = fmaxf(amx, fabsf(y));
        }
        #pragma unroll
        for (int m = 1; m < 16; m <<= 1)
            amx = fmaxf(amx, __shfl_xor_sync(0xffffffffu, amx, m));
        float amc = fmaxf(amx, 1e-5f);
        float s = 127.0f / amc;
        if (tj2 == 0) s_c3[tok] = (1.0f / s) * dq3;
        int p = (qact(h[0] * s) & 0xff)
              | ((qact(h[1] * s) & 0xff) << 8)
              | ((qact(h[2] * s) & 0xff) << 16)
              | ((qact(h[3] * s) & 0xff) << 24);
        s_h2q[tok * G3 + tj2] = p;
    }
    __syncthreads();

    // ---- GEMM3: [32 x 10], write output ----
    for (int p = t; p < MT * N3; p += NT) {
        int ltok = p / N3, j = p % N3;
        int a3 = 0;
        #pragma unroll
        for (int g = 0; g < G3; g++)
            a3 = __dp4a(s_h2q[ltok * G3 + g], g_wq3[j * G3 + g], a3);
        out[(blockIdx.x * MT + ltok) * N3 + j] = (float)a3 * s_c3[ltok];
    }
}

extern "C" void kernel_launch(void* const* d_in, const int* in_sizes, int n_in,
                              void* d_out, int out_size) {
    const float* x   = (const float*)d_in[0];
    const float* w1  = (const float*)d_in[1];
    const float* sc1 = (const float*)d_in[2];
    const float* w2  = (const float*)d_in[3];
    const float* sc2 = (const float*)d_in[4];
    const float* w3  = (const float*)d_in[5];
    const float* sc3 = (const float*)d_in[6];
    float* out = (float*)d_out;

    int ntok = in_sizes[0] / D1;   // 65536

    prep_partial<<<NPART, NT>>>(w1, w2, w3);
    prep_finalize<<<1, NT>>>(w2, w3);
    prep_quant_w1<<<(KC * NTILES * 32 * 2 + NT - 1) / NT, NT>>>(w1);
    ffn_main<<<ntok / MT, NT>>>(x, sc1, sc2, sc3, out);
}